// round 12
// baseline (speedup 1.0000x reference)
#include <cuda_runtime.h>
#include <cuda_bf16.h>
#include <cuda_fp16.h>
#include <math.h>
#include <float.h>

// Problem constants
#define BB   4
#define LL   2048
#define KNB  30
#define IND  128
#define OUTD 400
#define NROW (BB*LL)            // 8192

// Scratch (device globals; no allocation allowed)
__device__ __align__(16) float  g_A [NROW*OUTD];   // V@W1 + bias (fp32)
__device__ __align__(16) __half g_Bh[NROW*OUTD];   // V@W2 (fp16)
__device__ int g_E[NROW*KNB];

#define JSENT 2047

// lexicographic (f, j) compare-swap (stable for equal f by index)
#define SWP(fa,ja,fb,jb) do {                                        \
    if ((fa) > (fb) || ((fa) == (fb) && (ja) > (jb))) {              \
        float tf_=(fa); (fa)=(fb); (fb)=tf_;                         \
        int   tj_=(ja); (ja)=(jb); (jb)=tj_; }                       \
} while (0)

// ---------------------------------------------------------------------------
// KNN: one warp per query, 8 queries per 256-thread block, 1024 blocks.
// Planar x/y/z smem (24KB) + 256B validity bitmask -> 8 blocks/SM.
// Lane l owns candidates j = c*32 + l (conflict-free LDS.32).
// Hot loop: per-lane top-4 by squared distance in (float,int) registers;
// j strictly increases in the scan so strict float compares reproduce exact
// (value, index) lexicographic semantics. Survivors get sqrt + re-sort;
// selection = 30 rounds of two REDUX.MIN.
// ---------------------------------------------------------------------------
__global__ __launch_bounds__(256, 8) void knn_kernel(const float* __restrict__ X,
                           const float* __restrict__ mask,
                           float* __restrict__ tail, int writeTail)
{
    __shared__ float sx[LL], sy[LL], sz[LL];   // 24 KB
    __shared__ unsigned sBits[LL/32];          // 256 B validity bits

    int tid  = threadIdx.x;
    int w    = tid >> 5;             // 0..7
    int lane = tid & 31;
    int qblock = blockIdx.x * 8;
    int b = qblock >> 11;            // 256 blocks per batch: never crosses

    int ok = 1;
    #pragma unroll
    for (int it = 0; it < LL/256; it++) {
        int j = it*256 + tid;
        const float* xr = X + ((size_t)(b*LL + j))*12 + 3;
        sx[j] = xr[0];
        sy[j] = xr[1];
        sz[j] = xr[2];
        float mv = mask[b*LL + j];
        unsigned bal = __ballot_sync(0xffffffffu, mv == 1.0f);
        if (lane == 0) sBits[it*8 + w] = bal;
        ok &= (mv == 1.0f);
    }
    const int allValid = __syncthreads_and(ok);

    int q = qblock + w;
    int i = q & (LL-1);
    float qx = sx[i], qy = sy[i], qz = sz[i];
    bool qvalid = allValid || ((sBits[i>>5] >> (i&31)) & 1u);

    // masked-case row max (skipped entirely when the whole batch is valid)
    float dmax = 0.f;
    if (!allValid) {
        float maxsq = -1.f;
        for (int c = 0; c < 64; c++) {
            int j = c*32 + lane;
            float dx = sx[j]-qx, dy = sy[j]-qy, dz = sz[j]-qz;
            float sq = fmaf(dx,dx, fmaf(dy,dy, fmaf(dz,dz, 1e-6f)));
            bool vj = (sBits[c] >> lane) & 1u;
            if (qvalid && vj) maxsq = fmaxf(maxsq, sq);
        }
        #pragma unroll
        for (int off = 16; off; off >>= 1)
            maxsq = fmaxf(maxsq, __shfl_xor_sync(0xffffffffu, maxsq, off));
        dmax = (maxsq > 0.f) ? sqrtf(maxsq) : 0.f;
    }

    // hot loop: per-lane sorted top-4 ascending by (f, j); f is sq (allValid)
    float f0 = FLT_MAX, f1 = FLT_MAX, f2 = FLT_MAX, f3 = FLT_MAX;
    int   j0 = JSENT,   j1 = JSENT,   j2 = JSENT,   j3 = JSENT;
    #pragma unroll 8
    for (int c = 0; c < 64; c++) {
        int j = c*32 + lane;
        float dx = sx[j]-qx, dy = sy[j]-qy, dz = sz[j]-qz;
        float sq = fmaf(dx,dx, fmaf(dy,dy, fmaf(dz,dz, 1e-6f)));
        float dv;
        if (allValid) dv = sq;                           // sqrt deferred
        else {
            bool vj = (sBits[c] >> lane) & 1u;
            dv = (qvalid && vj) ? sqrtf(sq) : dmax;
        }
        if (dv < f3) {
            f3 = dv; j3 = j;
            if (f3 < f2) { float t=f2; f2=f3; f3=t; int u=j2; j2=j3; j3=u; }
            if (f2 < f1) { float t=f1; f1=f2; f2=t; int u=j1; j1=j2; j2=u; }
            if (f1 < f0) { float t=f0; f0=f1; f1=t; int u=j0; j0=j1; j1=u; }
        }
    }
    // convert survivors to sqrt domain and restore exact (f, j) order
    if (allValid) { f0 = sqrtf(f0); f1 = sqrtf(f1); f2 = sqrtf(f2); f3 = sqrtf(f3); }
    SWP(f0,j0,f1,j1); SWP(f2,j2,f3,j3); SWP(f0,j0,f2,j2); SWP(f1,j1,f3,j3); SWP(f1,j1,f2,j2);

    unsigned long long popped = 0ull;

    #pragma unroll 1
    for (int k = 0; k < KNB; k++) {
        unsigned kf = __float_as_uint(f0);              // nonneg -> monotone bits
        unsigned m  = __reduce_min_sync(0xffffffffu, kf);
        unsigned cand = (kf == m) ? (unsigned)j0 : 0xFFFFFFFFu;
        unsigned wj = __reduce_min_sync(0xffffffffu, cand);
        if (lane == 0) {
            g_E[q*KNB + k] = (int)wj;
            if (writeTail) tail[q*KNB + k] = (float)wj;
        }
        if ((wj & 31u) == (unsigned)lane) {             // owner pops its head
            popped |= 1ull << (wj >> 5);
            f0=f1; j0=j1; f1=f2; j1=j2; f2=f3; j2=j3; f3=FLT_MAX; j3=JSENT;
            if (f0 == FLT_MAX) {
                // refill (rare): rescan un-popped candidates
                for (int c = 0; c < 64; c++) {
                    if (popped & (1ull << c)) continue;
                    int j = c*32 + lane;
                    float dx = sx[j]-qx, dy = sy[j]-qy, dz = sz[j]-qz;
                    float sq = fmaf(dx,dx, fmaf(dy,dy, fmaf(dz,dz, 1e-6f)));
                    float dv;
                    if (allValid) dv = sq;
                    else {
                        bool vj = (sBits[c] >> lane) & 1u;
                        dv = (qvalid && vj) ? sqrtf(sq) : dmax;
                    }
                    if (dv < f3) {
                        f3 = dv; j3 = j;
                        if (f3 < f2) { float t=f2; f2=f3; f3=t; int u=j2; j2=j3; j3=u; }
                        if (f2 < f1) { float t=f1; f1=f2; f2=t; int u=j1; j1=j2; j2=u; }
                        if (f1 < f0) { float t=f0; f0=f1; f1=t; int u=j0; j0=j1; j1=u; }
                    }
                }
                if (allValid) { f0=sqrtf(f0); f1=sqrtf(f1); f2=sqrtf(f2); f3=sqrtf(f3); }
                SWP(f0,j0,f1,j1); SWP(f2,j2,f3,j3); SWP(f0,j0,f2,j2);
                SWP(f1,j1,f3,j3); SWP(f1,j1,f2,j2);
            }
        }
    }
}

// ---------------------------------------------------------------------------
// GEMM: g_A = V @ W[:128] + bias (fp32) ; g_Bh = V @ W[128:] (fp16)
// ---------------------------------------------------------------------------
__global__ void gemm_kernel(const float* __restrict__ V,
                            const float* __restrict__ W,
                            const float* __restrict__ bias)
{
    __shared__ float sV[16][132];
    __shared__ float sW[16][64];

    int rb   = blockIdx.x * 128;
    int cb   = blockIdx.y;
    int half = (cb >= 7) ? 1 : 0;
    int o0   = (cb - half*7) * 64;
    int koff = half * 128;

    int tid = threadIdx.x;
    int ty = tid >> 4;
    int tx = tid & 15;

    float acc[8][4];
    #pragma unroll
    for (int r = 0; r < 8; r++)
        #pragma unroll
        for (int c = 0; c < 4; c++) acc[r][c] = 0.f;

    for (int kt = 0; kt < IND; kt += 16) {
        {
            int rr = tid & 127;
            int v  = tid >> 7;
            const float* src = V + (size_t)(rb + rr)*IND + kt + v*8;
            float4 a  = *(const float4*)src;
            float4 b2 = *(const float4*)(src + 4);
            int kk = v * 8;
            sV[kk+0][rr]=a.x;  sV[kk+1][rr]=a.y;  sV[kk+2][rr]=a.z;  sV[kk+3][rr]=a.w;
            sV[kk+4][rr]=b2.x; sV[kk+5][rr]=b2.y; sV[kk+6][rr]=b2.z; sV[kk+7][rr]=b2.w;
        }
        {
            int kk = tid >> 4;
            int cc = (tid & 15) * 4;
            int o  = o0 + cc;
            const float* wrow = W + (size_t)(kt + kk + koff)*OUTD;
            float4 wv;
            if (o + 3 < OUTD) {
                wv = *(const float4*)(wrow + o);
            } else {
                wv.x = (o+0 < OUTD) ? wrow[o+0] : 0.f;
                wv.y = (o+1 < OUTD) ? wrow[o+1] : 0.f;
                wv.z = (o+2 < OUTD) ? wrow[o+2] : 0.f;
                wv.w = (o+3 < OUTD) ? wrow[o+3] : 0.f;
            }
            *(float4*)&sW[kk][cc] = wv;
        }
        __syncthreads();

        #pragma unroll
        for (int kk = 0; kk < 16; kk++) {
            float rv[8];
            *(float4*)&rv[0] = *(const float4*)&sV[kk][ty*8];
            *(float4*)&rv[4] = *(const float4*)&sV[kk][ty*8 + 4];
            float4 wv = *(const float4*)&sW[kk][tx*4];
            #pragma unroll
            for (int r = 0; r < 8; r++) {
                acc[r][0] += rv[r] * wv.x;
                acc[r][1] += rv[r] * wv.y;
                acc[r][2] += rv[r] * wv.z;
                acc[r][3] += rv[r] * wv.w;
            }
        }
        __syncthreads();
    }

    #pragma unroll
    for (int r = 0; r < 8; r++) {
        int row = rb + ty*8 + r;
        int o = o0 + tx*4;
        if (o < OUTD) {
            if (!half) {
                float4 v;
                v.x = acc[r][0] + bias[o+0];
                v.y = acc[r][1] + bias[o+1];
                v.z = acc[r][2] + bias[o+2];
                v.w = acc[r][3] + bias[o+3];
                *(float4*)&g_A[(size_t)row*OUTD + o] = v;
            } else {
                __half2 h0 = __floats2half2_rn(acc[r][0], acc[r][1]);
                __half2 h1 = __floats2half2_rn(acc[r][2], acc[r][3]);
                __half2* dst = (__half2*)&g_Bh[(size_t)row*OUTD + o];
                dst[0] = h0;
                dst[1] = h1;
            }
        }
    }
}

// ---------------------------------------------------------------------------
// Assembly: out[q,k,:] = A_fp32[row_i0,:] + Bm_fp16[row_jk,:]
// 2 queries per 512-thread block; fp16 gathers halve the L2 read stream;
// __stcs streaming stores keep the 393MB output from evicting gather tables.
// ---------------------------------------------------------------------------
__global__ __launch_bounds__(512) void assemble_kernel(float* __restrict__ out)
{
    __shared__ float4 sA[2][100];
    __shared__ int    sI[2][KNB];

    int tid  = threadIdx.x;
    int half = tid >> 8;            // which query within block
    int t    = tid & 255;
    int q    = blockIdx.x * 2 + half;
    int b    = q >> 11;

    if (t < KNB) sI[half][t] = g_E[q*KNB + t];
    __syncthreads();
    int e0 = sI[half][0];
    if (t < 100)
        sA[half][t] = ((const float4*)g_A)[(size_t)((b << 11) + e0)*100 + t];
    __syncthreads();

    float4* out4 = (float4*)out + (size_t)q * (KNB*100);
    const uint4* Bh4 = (const uint4*)g_Bh;     // 8 halves per uint4, 50 per row

    #pragma unroll
    for (int it = 0; it < 6; it++) {
        int id = t + it*256;                   // over KNB*50 = 1500 chunks
        if (id < KNB*50) {
            int k = id / 50;
            int c = id - k*50;                 // half-chunk within row (8 halves)
            int rj = (b << 11) + sI[half][k];
            uint4 h = __ldg(&Bh4[(size_t)rj*50 + c]);
            float4 a0 = sA[half][c*2];
            float4 a1 = sA[half][c*2 + 1];
            float2 p0 = __half22float2(*(__half2*)&h.x);
            float2 p1 = __half22float2(*(__half2*)&h.y);
            float2 p2 = __half22float2(*(__half2*)&h.z);
            float2 p3 = __half22float2(*(__half2*)&h.w);
            float4 r0, r1;
            r0.x = a0.x + p0.x; r0.y = a0.y + p0.y;
            r0.z = a0.z + p1.x; r0.w = a0.w + p1.y;
            r1.x = a1.x + p2.x; r1.y = a1.y + p2.y;
            r1.z = a1.z + p3.x; r1.w = a1.w + p3.y;
            __stcs(&out4[k*100 + c*2],     r0);
            __stcs(&out4[k*100 + c*2 + 1], r1);
        }
    }
}

// ---------------------------------------------------------------------------
extern "C" void kernel_launch(void* const* d_in, const int* in_sizes, int n_in,
                              void* d_out, int out_size)
{
    const float* X    = (const float*)d_in[0];
    const float* mask = (const float*)d_in[1];
    const float* V    = (const float*)d_in[2];
    const float* W    = (const float*)d_in[3];
    const float* bias = (const float*)d_in[4];
    float* out = (float*)d_out;

    const long long HEV  = (long long)NROW * KNB * OUTD;  // 98,304,000
    const long long EIDX = (long long)NROW * KNB;         // 245,760
    int writeTail = ((long long)out_size >= HEV + EIDX) ? 1 : 0;
    float* tail = writeTail ? (out + HEV) : nullptr;

    // one-time side-stream setup (no device memory involved)
    static cudaStream_t s2 = nullptr;
    static cudaEvent_t eFork = nullptr, eJoin = nullptr;
    static int streamsOK = -1;
    if (streamsOK < 0) {
        streamsOK = 1;
        if (cudaStreamCreateWithFlags(&s2, cudaStreamNonBlocking) != cudaSuccess) streamsOK = 0;
        if (streamsOK && cudaEventCreateWithFlags(&eFork, cudaEventDisableTiming) != cudaSuccess) streamsOK = 0;
        if (streamsOK && cudaEventCreateWithFlags(&eJoin, cudaEventDisableTiming) != cudaSuccess) streamsOK = 0;
    }

    if (streamsOK) {
        // fork: gemm runs concurrently with knn
        cudaEventRecord(eFork, 0);
        cudaStreamWaitEvent(s2, eFork, 0);
        knn_kernel<<<NROW/8, 256>>>(X, mask, tail, writeTail);
        gemm_kernel<<<dim3(NROW/128, 14), 256, 0, s2>>>(V, W, bias);
        cudaEventRecord(eJoin, s2);
        cudaStreamWaitEvent(0, eJoin, 0);
        assemble_kernel<<<NROW/2, 512>>>(out);
    } else {
        knn_kernel<<<NROW/8, 256>>>(X, mask, tail, writeTail);
        gemm_kernel<<<dim3(NROW/128, 14), 256>>>(V, W, bias);
        assemble_kernel<<<NROW/2, 512>>>(out);
    }
}

// round 13
// speedup vs baseline: 1.2915x; 1.2915x over previous
#include <cuda_runtime.h>
#include <cuda_bf16.h>
#include <cuda_fp16.h>
#include <math.h>
#include <float.h>

// Problem constants
#define BB   4
#define LL   2048
#define KNB  30
#define IND  128
#define OUTD 400
#define NROW (BB*LL)            // 8192

// Scratch (device globals; no allocation allowed)
__device__ __align__(16) float  g_A [NROW*OUTD];   // V@W1 + bias (fp32)
__device__ __align__(16) __half g_Bh[NROW*OUTD];   // V@W2 (fp16)
__device__ int g_E[NROW*KNB];

#define JSENT 2047

// lexicographic (f, j) compare-swap (stable for equal f by index)
#define SWP(fa,ja,fb,jb) do {                                        \
    if ((fa) > (fb) || ((fa) == (fb) && (ja) > (jb))) {              \
        float tf_=(fa); (fa)=(fb); (fb)=tf_;                         \
        int   tj_=(ja); (ja)=(jb); (jb)=tj_; }                       \
} while (0)

// ---------------------------------------------------------------------------
// KNN (round-11 winner): one warp per query, 16 queries per 512-thread block.
// Lane l owns candidates j = c*32 + l (conflict-free LDS.128).
// Hot loop: per-lane top-4 by squared distance in (float,int) registers;
// j strictly increases in the scan so strict float compares reproduce exact
// (value, index) lexicographic semantics. Survivors get sqrt + re-sort;
// selection = 30 rounds of two REDUX.MIN.
// ---------------------------------------------------------------------------
__global__ __launch_bounds__(512, 4) void knn_kernel(const float* __restrict__ X,
                           const float* __restrict__ mask,
                           float* __restrict__ tail, int writeTail)
{
    __shared__ float4 sX[LL];        // (x, y, z, mask)  32 KB
    __shared__ int sAllValid;

    int tid  = threadIdx.x;
    int w    = tid >> 5;             // 0..15
    int lane = tid & 31;
    int qblock = blockIdx.x * 16;
    int b = qblock >> 11;            // 128 blocks per batch: never crosses

    if (tid == 0) sAllValid = 1;
    __syncthreads();

    int ok = 1;
    for (int j = tid; j < LL; j += 512) {
        const float* xr = X + ((size_t)(b*LL + j))*12 + 3;
        float mv = mask[b*LL + j];
        sX[j] = make_float4(xr[0], xr[1], xr[2], mv);
        ok &= (mv == 1.0f);
    }
    if (!ok) sAllValid = 0;
    __syncthreads();

    const int allValid = sAllValid;

    int q = qblock + w;
    int i = q & (LL-1);
    float4 qp = sX[i];
    float qx = qp.x, qy = qp.y, qz = qp.z;
    bool qvalid = allValid || (qp.w > 0.5f);

    // masked-case row max (skipped entirely when the whole batch is valid)
    float dmax = 0.f;
    if (!allValid) {
        float maxsq = -1.f;
        for (int c = 0; c < 64; c++) {
            int j = c*32 + lane;
            float4 p = sX[j];
            float dx = p.x-qx, dy = p.y-qy, dz = p.z-qz;
            float sq = fmaf(dx,dx, fmaf(dy,dy, fmaf(dz,dz, 1e-6f)));
            if (qvalid && (p.w > 0.5f)) maxsq = fmaxf(maxsq, sq);
        }
        #pragma unroll
        for (int off = 16; off; off >>= 1)
            maxsq = fmaxf(maxsq, __shfl_xor_sync(0xffffffffu, maxsq, off));
        dmax = (maxsq > 0.f) ? sqrtf(maxsq) : 0.f;
    }

    // hot loop: per-lane sorted top-4 ascending by (f, j); f is sq (allValid)
    float f0 = FLT_MAX, f1 = FLT_MAX, f2 = FLT_MAX, f3 = FLT_MAX;
    int   j0 = JSENT,   j1 = JSENT,   j2 = JSENT,   j3 = JSENT;
    #pragma unroll 8
    for (int c = 0; c < 64; c++) {
        int j = c*32 + lane;
        float4 p = sX[j];
        float dx = p.x-qx, dy = p.y-qy, dz = p.z-qz;
        float sq = fmaf(dx,dx, fmaf(dy,dy, fmaf(dz,dz, 1e-6f)));
        float dv;
        if (allValid) dv = sq;                           // sqrt deferred
        else dv = (qvalid && (p.w > 0.5f)) ? sqrtf(sq) : dmax;
        if (dv < f3) {
            f3 = dv; j3 = j;
            if (f3 < f2) { float t=f2; f2=f3; f3=t; int u=j2; j2=j3; j3=u; }
            if (f2 < f1) { float t=f1; f1=f2; f2=t; int u=j1; j1=j2; j2=u; }
            if (f1 < f0) { float t=f0; f0=f1; f1=t; int u=j0; j0=j1; j1=u; }
        }
    }
    // convert survivors to sqrt domain and restore exact (f, j) order
    if (allValid) { f0 = sqrtf(f0); f1 = sqrtf(f1); f2 = sqrtf(f2); f3 = sqrtf(f3); }
    SWP(f0,j0,f1,j1); SWP(f2,j2,f3,j3); SWP(f0,j0,f2,j2); SWP(f1,j1,f3,j3); SWP(f1,j1,f2,j2);

    unsigned long long popped = 0ull;

    #pragma unroll 1
    for (int k = 0; k < KNB; k++) {
        unsigned kf = __float_as_uint(f0);              // nonneg -> monotone bits
        unsigned m  = __reduce_min_sync(0xffffffffu, kf);
        unsigned cand = (kf == m) ? (unsigned)j0 : 0xFFFFFFFFu;
        unsigned wj = __reduce_min_sync(0xffffffffu, cand);
        if (lane == 0) {
            g_E[q*KNB + k] = (int)wj;
            if (writeTail) tail[q*KNB + k] = (float)wj;
        }
        if ((wj & 31u) == (unsigned)lane) {             // owner pops its head
            popped |= 1ull << (wj >> 5);
            f0=f1; j0=j1; f1=f2; j1=j2; f2=f3; j2=j3; f3=FLT_MAX; j3=JSENT;
            if (f0 == FLT_MAX) {
                // refill (rare): rescan un-popped candidates
                for (int c = 0; c < 64; c++) {
                    if (popped & (1ull << c)) continue;
                    int j = c*32 + lane;
                    float4 p = sX[j];
                    float dx = p.x-qx, dy = p.y-qy, dz = p.z-qz;
                    float sq = fmaf(dx,dx, fmaf(dy,dy, fmaf(dz,dz, 1e-6f)));
                    float dv;
                    if (allValid) dv = sq;
                    else dv = (qvalid && (p.w > 0.5f)) ? sqrtf(sq) : dmax;
                    if (dv < f3) {
                        f3 = dv; j3 = j;
                        if (f3 < f2) { float t=f2; f2=f3; f3=t; int u=j2; j2=j3; j3=u; }
                        if (f2 < f1) { float t=f1; f1=f2; f2=t; int u=j1; j1=j2; j2=u; }
                        if (f1 < f0) { float t=f0; f0=f1; f1=t; int u=j0; j0=j1; j1=u; }
                    }
                }
                if (allValid) { f0=sqrtf(f0); f1=sqrtf(f1); f2=sqrtf(f2); f3=sqrtf(f3); }
                SWP(f0,j0,f1,j1); SWP(f2,j2,f3,j3); SWP(f0,j0,f2,j2);
                SWP(f1,j1,f3,j3); SWP(f1,j1,f2,j2);
            }
        }
    }
}

// ---------------------------------------------------------------------------
// GEMM: g_A = V @ W[:128] + bias (fp32) ; g_Bh = V @ W[128:] (fp16)
// ---------------------------------------------------------------------------
__global__ void gemm_kernel(const float* __restrict__ V,
                            const float* __restrict__ W,
                            const float* __restrict__ bias)
{
    __shared__ float sV[16][132];
    __shared__ float sW[16][64];

    int rb   = blockIdx.x * 128;
    int cb   = blockIdx.y;
    int half = (cb >= 7) ? 1 : 0;
    int o0   = (cb - half*7) * 64;
    int koff = half * 128;

    int tid = threadIdx.x;
    int ty = tid >> 4;
    int tx = tid & 15;

    float acc[8][4];
    #pragma unroll
    for (int r = 0; r < 8; r++)
        #pragma unroll
        for (int c = 0; c < 4; c++) acc[r][c] = 0.f;

    for (int kt = 0; kt < IND; kt += 16) {
        {
            int rr = tid & 127;
            int v  = tid >> 7;
            const float* src = V + (size_t)(rb + rr)*IND + kt + v*8;
            float4 a  = *(const float4*)src;
            float4 b2 = *(const float4*)(src + 4);
            int kk = v * 8;
            sV[kk+0][rr]=a.x;  sV[kk+1][rr]=a.y;  sV[kk+2][rr]=a.z;  sV[kk+3][rr]=a.w;
            sV[kk+4][rr]=b2.x; sV[kk+5][rr]=b2.y; sV[kk+6][rr]=b2.z; sV[kk+7][rr]=b2.w;
        }
        {
            int kk = tid >> 4;
            int cc = (tid & 15) * 4;
            int o  = o0 + cc;
            const float* wrow = W + (size_t)(kt + kk + koff)*OUTD;
            float4 wv;
            if (o + 3 < OUTD) {
                wv = *(const float4*)(wrow + o);
            } else {
                wv.x = (o+0 < OUTD) ? wrow[o+0] : 0.f;
                wv.y = (o+1 < OUTD) ? wrow[o+1] : 0.f;
                wv.z = (o+2 < OUTD) ? wrow[o+2] : 0.f;
                wv.w = (o+3 < OUTD) ? wrow[o+3] : 0.f;
            }
            *(float4*)&sW[kk][cc] = wv;
        }
        __syncthreads();

        #pragma unroll
        for (int kk = 0; kk < 16; kk++) {
            float rv[8];
            *(float4*)&rv[0] = *(const float4*)&sV[kk][ty*8];
            *(float4*)&rv[4] = *(const float4*)&sV[kk][ty*8 + 4];
            float4 wv = *(const float4*)&sW[kk][tx*4];
            #pragma unroll
            for (int r = 0; r < 8; r++) {
                acc[r][0] += rv[r] * wv.x;
                acc[r][1] += rv[r] * wv.y;
                acc[r][2] += rv[r] * wv.z;
                acc[r][3] += rv[r] * wv.w;
            }
        }
        __syncthreads();
    }

    #pragma unroll
    for (int r = 0; r < 8; r++) {
        int row = rb + ty*8 + r;
        int o = o0 + tx*4;
        if (o < OUTD) {
            if (!half) {
                float4 v;
                v.x = acc[r][0] + bias[o+0];
                v.y = acc[r][1] + bias[o+1];
                v.z = acc[r][2] + bias[o+2];
                v.w = acc[r][3] + bias[o+3];
                *(float4*)&g_A[(size_t)row*OUTD + o] = v;
            } else {
                __half2 h0 = __floats2half2_rn(acc[r][0], acc[r][1]);
                __half2 h1 = __floats2half2_rn(acc[r][2], acc[r][3]);
                uint2 pk;
                pk.x = *(unsigned*)&h0;
                pk.y = *(unsigned*)&h1;
                *(uint2*)&g_Bh[(size_t)row*OUTD + o] = pk;   // one 8B store
            }
        }
    }
}

// ---------------------------------------------------------------------------
// Assembly: out[q,k,:] = A_fp32[row_i0,:] + Bh_fp16[row_jk,:]
// Round-11 store pattern (one coalesced float4 per thread), fp16 8B gathers
// halve the L2 read stream. __stcs keeps the 393MB output stream from
// evicting the L2-resident gather tables.
// ---------------------------------------------------------------------------
__global__ __launch_bounds__(512) void assemble_kernel(float* __restrict__ out)
{
    __shared__ float4 sA[2][100];
    __shared__ int    sI[2][KNB];

    int tid  = threadIdx.x;
    int half = tid >> 8;            // which query within block
    int t    = tid & 255;
    int q    = blockIdx.x * 2 + half;
    int b    = q >> 11;

    if (t < KNB) sI[half][t] = g_E[q*KNB + t];
    __syncthreads();
    int e0 = sI[half][0];
    if (t < 100)
        sA[half][t] = ((const float4*)g_A)[(size_t)((b << 11) + e0)*100 + t];
    __syncthreads();

    float4* out4 = (float4*)out + (size_t)q * (KNB*100);
    const uint2* Bh2 = (const uint2*)g_Bh;   // 4 halves per uint2, 100 per row

    #pragma unroll
    for (int it = 0; it < 12; it++) {
        int id = t + it*256;                 // over KNB*100 = 3000 float4 chunks
        if (id < KNB*100) {
            int k = id / 100;
            int c = id - k*100;
            int rj = (b << 11) + sI[half][k];
            uint2 h = __ldg(&Bh2[(size_t)rj*100 + c]);
            float2 p0 = __half22float2(*(__half2*)&h.x);
            float2 p1 = __half22float2(*(__half2*)&h.y);
            float4 a = sA[half][c];
            float4 r;
            r.x = a.x + p0.x; r.y = a.y + p0.y;
            r.z = a.z + p1.x; r.w = a.w + p1.y;
            __stcs(&out4[id], r);
        }
    }
}

// ---------------------------------------------------------------------------
extern "C" void kernel_launch(void* const* d_in, const int* in_sizes, int n_in,
                              void* d_out, int out_size)
{
    const float* X    = (const float*)d_in[0];
    const float* mask = (const float*)d_in[1];
    const float* V    = (const float*)d_in[2];
    const float* W    = (const float*)d_in[3];
    const float* bias = (const float*)d_in[4];
    float* out = (float*)d_out;

    const long long HEV  = (long long)NROW * KNB * OUTD;  // 98,304,000
    const long long EIDX = (long long)NROW * KNB;         // 245,760
    int writeTail = ((long long)out_size >= HEV + EIDX) ? 1 : 0;
    float* tail = writeTail ? (out + HEV) : nullptr;

    // one-time side-stream setup (no device memory involved)
    static cudaStream_t s2 = nullptr;
    static cudaEvent_t eFork = nullptr, eJoin = nullptr;
    static int streamsOK = -1;
    if (streamsOK < 0) {
        streamsOK = 1;
        if (cudaStreamCreateWithFlags(&s2, cudaStreamNonBlocking) != cudaSuccess) streamsOK = 0;
        if (streamsOK && cudaEventCreateWithFlags(&eFork, cudaEventDisableTiming) != cudaSuccess) streamsOK = 0;
        if (streamsOK && cudaEventCreateWithFlags(&eJoin, cudaEventDisableTiming) != cudaSuccess) streamsOK = 0;
    }

    if (streamsOK) {
        // fork: gemm runs concurrently with knn
        cudaEventRecord(eFork, 0);
        cudaStreamWaitEvent(s2, eFork, 0);
        knn_kernel<<<NROW/16, 512>>>(X, mask, tail, writeTail);
        gemm_kernel<<<dim3(NROW/128, 14), 256, 0, s2>>>(V, W, bias);
        cudaEventRecord(eJoin, s2);
        cudaStreamWaitEvent(0, eJoin, 0);
        assemble_kernel<<<NROW/2, 512>>>(out);
    } else {
        knn_kernel<<<NROW/16, 512>>>(X, mask, tail, writeTail);
        gemm_kernel<<<dim3(NROW/128, 14), 256>>>(V, W, bias);
        assemble_kernel<<<NROW/2, 512>>>(out);
    }
}